// round 1
// baseline (speedup 1.0000x reference)
#include <cuda_runtime.h>
#include <cuda_bf16.h>

// PerformerHead: algebraic reduction.
// Causal linear attention output at position 0 equals v at position 0 exactly
// (attn[0,0]*v0 / attn[0,0]); the final classifier reads only h[:,0,:].
// Therefore the whole model reduces, per batch, to a 256-dim vector pushed
// through 4 residual blocks:
//   h += LN1(h) @ wv @ wo + bo
//   h += gelu(LN2(h) @ w1 + b1) @ w2 + b2
// seeded with emb_tok[x[b,0]] + emb_pos[0], followed by h @ w_cls + b_cls.
// proj / wq / wk and positions 1..N-1 are dead code for this output.

#define DMODEL 256
#define DHID   1024
#define NLAYER 4
#define NT     1024

// Block-wide sum over all 1024 threads (32 warps). All threads must call.
__device__ __forceinline__ float blocksum(float v, float* red) {
    #pragma unroll
    for (int o = 16; o > 0; o >>= 1) v += __shfl_xor_sync(0xffffffffu, v, o);
    const int lane = threadIdx.x & 31, warp = threadIdx.x >> 5;
    if (lane == 0) red[warp] = v;
    __syncthreads();
    if (warp == 0) {
        float s = red[lane];
        #pragma unroll
        for (int o = 16; o > 0; o >>= 1) s += __shfl_xor_sync(0xffffffffu, s, o);
        if (lane == 0) red[0] = s;
    }
    __syncthreads();
    float s = red[0];
    __syncthreads();           // protect red[] for the next reduction
    return s;
}

// y = LN(h) * scale + bias   (eps = 1e-5, matching reference layer_norm)
__device__ __forceinline__ void layernorm(const float* __restrict__ h,
                                          float* __restrict__ y,
                                          const float* __restrict__ s,
                                          const float* __restrict__ b,
                                          float* red, int t) {
    float xv = (t < DMODEL) ? h[t] : 0.0f;
    float mu = blocksum(xv, red) * (1.0f / DMODEL);
    float d  = (t < DMODEL) ? (xv - mu) : 0.0f;
    float var = blocksum(d * d, red) * (1.0f / DMODEL);
    float inv = rsqrtf(var + 1e-5f);
    if (t < DMODEL) y[t] = d * inv * s[t] + b[t];
    __syncthreads();
}

// out[j] = sum_i in[i] * W[i*256 + j]   (+ bias), 4-way K-split over 1024 thr.
__device__ __forceinline__ void mm256x256(const float* __restrict__ in,
                                          const float* __restrict__ W,
                                          const float* __restrict__ bias,
                                          float* __restrict__ out,
                                          float* tmp, int t) {
    const int j = t & (DMODEL - 1);
    const int q = t >> 8;                   // 0..3, 64 k-values each
    const float* Wp = W + (size_t)(q * 64) * DMODEL + j;
    const float* ip = in + q * 64;
    float acc = 0.0f;
    #pragma unroll 8
    for (int i = 0; i < 64; i++) acc += ip[i] * Wp[(size_t)i * DMODEL];
    tmp[t] = acc;
    __syncthreads();
    if (t < DMODEL) {
        float r = tmp[t] + tmp[t + 256] + tmp[t + 512] + tmp[t + 768];
        if (bias) r += bias[t];
        out[t] = r;
    }
    __syncthreads();
}

__global__ __launch_bounds__(NT, 1)
void performer_tok0_kernel(const int* __restrict__ x, int N,
                           const float* __restrict__ emb_tok,
                           const float* __restrict__ emb_pos,
                           const float* __restrict__ ln1_s,
                           const float* __restrict__ ln1_b,
                           const float* __restrict__ wv,
                           const float* __restrict__ wo,
                           const float* __restrict__ bo,
                           const float* __restrict__ ln2_s,
                           const float* __restrict__ ln2_b,
                           const float* __restrict__ w1,
                           const float* __restrict__ b1,
                           const float* __restrict__ w2,
                           const float* __restrict__ b2,
                           const float* __restrict__ wcls,
                           const float* __restrict__ bcls,
                           float* __restrict__ out) {
    __shared__ float h[DMODEL];
    __shared__ float y[DMODEL];
    __shared__ float u[DHID];
    __shared__ float tmp[NT];
    __shared__ float red[32];

    const int t = threadIdx.x;
    const int bidx = blockIdx.x;

    if (t < DMODEL) {
        const int tok = x[(size_t)bidx * N];          // x[b, 0]
        h[t] = emb_tok[(size_t)tok * DMODEL + t] + emb_pos[t];
    }
    __syncthreads();

    for (int l = 0; l < NLAYER; l++) {
        const float* ln1s = ln1_s + l * DMODEL;
        const float* ln1b = ln1_b + l * DMODEL;
        const float* Wv   = wv + (size_t)l * DMODEL * DMODEL;
        const float* Wo   = wo + (size_t)l * DMODEL * DMODEL;
        const float* Bo   = bo + l * DMODEL;
        const float* ln2s = ln2_s + l * DMODEL;
        const float* ln2b = ln2_b + l * DMODEL;
        const float* W1   = w1 + (size_t)l * DMODEL * DHID;
        const float* B1   = b1 + l * DHID;
        const float* W2   = w2 + (size_t)l * DHID * DMODEL;
        const float* B2   = b2 + l * DMODEL;

        // ---- attention path (reduced): h += LN1(h) @ Wv @ Wo + bo ----
        layernorm(h, y, ln1s, ln1b, red, t);
        mm256x256(y, Wv, nullptr, u, tmp, t);     // v0 -> u[0:256]
        mm256x256(u, Wo, Bo, y, tmp, t);          // o0 -> y
        if (t < DMODEL) h[t] += y[t];
        __syncthreads();

        // ---- MLP: h += gelu(LN2(h) @ W1 + b1) @ W2 + b2 ----
        layernorm(h, y, ln2s, ln2b, red, t);
        {
            // each of the 1024 threads owns one hidden unit
            const float* Wp = W1 + t;
            float acc = B1[t];
            #pragma unroll 8
            for (int i = 0; i < DMODEL; i++) acc += y[i] * Wp[(size_t)i * DHID];
            // jax.nn.gelu (approximate=True, tanh form)
            const float k0 = 0.7978845608028654f;   // sqrt(2/pi)
            float g = 0.5f * acc * (1.0f + tanhf(k0 * (acc + 0.044715f * acc * acc * acc)));
            u[t] = g;
        }
        __syncthreads();
        {
            const int j = t & (DMODEL - 1);
            const int q = t >> 8;                   // 256 k-values each
            const float* Wp = W2 + (size_t)(q * 256) * DMODEL + j;
            const float* up = u + q * 256;
            float acc = 0.0f;
            #pragma unroll 8
            for (int i = 0; i < 256; i++) acc += up[i] * Wp[(size_t)i * DMODEL];
            tmp[t] = acc;
            __syncthreads();
            if (t < DMODEL)
                h[t] += tmp[t] + tmp[t + 256] + tmp[t + 512] + tmp[t + 768] + B2[t];
            __syncthreads();
        }
    }

    // ---- classifier head: out[b] = h @ wcls + bcls  (C = 10) ----
    if (t < 10) {
        float acc = bcls[t];
        #pragma unroll 8
        for (int i = 0; i < DMODEL; i++) acc += h[i] * wcls[(size_t)i * 10 + t];
        out[(size_t)bidx * 10 + t] = acc;
    }
}

extern "C" void kernel_launch(void* const* d_in, const int* in_sizes, int n_in,
                              void* d_out, int out_size) {
    // metadata order:
    // 0:x(int32) 1:emb_tok 2:emb_pos 3:proj(unused) 4:ln1_s 5:ln1_b
    // 6:wq(unused) 7:wk(unused) 8:wv 9:wo 10:bo 11:ln2_s 12:ln2_b
    // 13:w1 14:b1 15:w2 16:b2 17:w_cls 18:b_cls
    const int*   x       = (const int*)  d_in[0];
    const float* emb_tok = (const float*)d_in[1];
    const float* emb_pos = (const float*)d_in[2];
    const float* ln1_s   = (const float*)d_in[4];
    const float* ln1_b   = (const float*)d_in[5];
    const float* wv      = (const float*)d_in[8];
    const float* wo      = (const float*)d_in[9];
    const float* bo      = (const float*)d_in[10];
    const float* ln2_s   = (const float*)d_in[11];
    const float* ln2_b   = (const float*)d_in[12];
    const float* w1      = (const float*)d_in[13];
    const float* b1      = (const float*)d_in[14];
    const float* w2      = (const float*)d_in[15];
    const float* b2      = (const float*)d_in[16];
    const float* wcls    = (const float*)d_in[17];
    const float* bcls    = (const float*)d_in[18];
    float* out = (float*)d_out;

    const int B = out_size / 10;          // 16
    const int N = in_sizes[0] / B;        // 4096

    performer_tok0_kernel<<<B, NT>>>(x, N, emb_tok, emb_pos,
                                     ln1_s, ln1_b, wv, wo, bo,
                                     ln2_s, ln2_b, w1, b1, w2, b2,
                                     wcls, bcls, out);
    (void)n_in;
}